// round 3
// baseline (speedup 1.0000x reference)
#include <cuda_runtime.h>
#include <cuda.h>
#include <cstdint>
#include <cstddef>

static constexpr int DMODEL  = 2048;
static constexpr int DHIDDEN = 8192;
static constexpr int TOKENS  = 8192;
static constexpr int NWELEM  = DMODEL * DHIDDEN;  // 2^24
#define EPSF 1e-5f

__device__ __align__(128) int8_t g_xq[(size_t)TOKENS * DMODEL];
__device__ __align__(128) int8_t g_w1q[(size_t)NWELEM];
__device__ __align__(128) int8_t g_w2q[(size_t)NWELEM];
__device__ __align__(128) float  g_h[(size_t)TOKENS * DHIDDEN];
__device__ __align__(128) int8_t g_hq[(size_t)TOKENS * DHIDDEN];
__device__ float g_rdq1[TOKENS];
__device__ float g_rdq2[TOKENS];
__device__ float g_wmean[2];
__device__ float g_part[4096];

__device__ __forceinline__ uint32_t smem_u32(const void* p) {
    uint32_t a;
    asm("{ .reg .u64 t; cvta.to.shared.u64 t, %1; cvt.u32.u64 %0, t; }" : "=r"(a) : "l"(p));
    return a;
}
#define CP_ASYNC16(dst, src) \
    asm volatile("cp.async.cg.shared.global [%0], [%1], 16;" :: "r"(dst), "l"(src) : "memory")
#define CP_COMMIT() asm volatile("cp.async.commit_group;" ::: "memory")
#define CP_WAIT(n)  asm volatile("cp.async.wait_group %0;" :: "n"(n) : "memory")

__device__ __forceinline__ void ldm_x4(uint32_t& r0, uint32_t& r1, uint32_t& r2, uint32_t& r3,
                                       uint32_t addr) {
    asm volatile("ldmatrix.sync.aligned.m8n8.x4.shared.b16 {%0,%1,%2,%3}, [%4];"
        : "=r"(r0), "=r"(r1), "=r"(r2), "=r"(r3) : "r"(addr));
}
__device__ __forceinline__ void imma(int* d, const uint32_t* a, uint32_t b0, uint32_t b1) {
    asm volatile(
        "mma.sync.aligned.m16n8k32.row.col.s32.s8.s8.s32 "
        "{%0,%1,%2,%3}, {%4,%5,%6,%7}, {%8,%9}, {%0,%1,%2,%3};"
        : "+r"(d[0]), "+r"(d[1]), "+r"(d[2]), "+r"(d[3])
        : "r"(a[0]), "r"(a[1]), "r"(a[2]), "r"(a[3]), "r"(b0), "r"(b1));
}

// ---------------- small kernels ----------------
__global__ void absmean_partial(const float* __restrict__ w, int n, float* __restrict__ part) {
    float s = 0.f;
    for (int i = blockIdx.x * blockDim.x + threadIdx.x; i < n; i += gridDim.x * blockDim.x)
        s += fabsf(w[i]);
    __shared__ float sh[256];
    sh[threadIdx.x] = s;
    __syncthreads();
    #pragma unroll
    for (int o = 128; o > 0; o >>= 1) {
        if (threadIdx.x < o) sh[threadIdx.x] += sh[threadIdx.x + o];
        __syncthreads();
    }
    if (threadIdx.x == 0) part[blockIdx.x] = sh[0];
}

__global__ void absmean_final(const float* __restrict__ part, float invn, float* __restrict__ outp) {
    float s = 0.f;
    for (int i = threadIdx.x; i < 2048; i += 256) s += part[i];
    __shared__ float sh[256];
    sh[threadIdx.x] = s;
    __syncthreads();
    #pragma unroll
    for (int o = 128; o > 0; o >>= 1) {
        if (threadIdx.x < o) sh[threadIdx.x] += sh[threadIdx.x + o];
        __syncthreads();
    }
    if (threadIdx.x == 0) outp[0] = fmaxf(s = sh[0] * invn, EPSF);
}

__global__ void quant_w(const float* __restrict__ w, const float* __restrict__ meanp,
                        int8_t* __restrict__ wq) {
    float sc = 1.0f / meanp[0];
    int i = blockIdx.x * blockDim.x + threadIdx.x;
    float4 v = reinterpret_cast<const float4*>(w)[i];
    char4 p;
    p.x = (char)(int)fminf(fmaxf(rintf(v.x * sc), -1.f), 1.f);
    p.y = (char)(int)fminf(fmaxf(rintf(v.y * sc), -1.f), 1.f);
    p.z = (char)(int)fminf(fmaxf(rintf(v.z * sc), -1.f), 1.f);
    p.w = (char)(int)fminf(fmaxf(rintf(v.w * sc), -1.f), 1.f);
    reinterpret_cast<char4*>(wq)[i] = p;
}

__device__ __forceinline__ int qcl(float f) {
    return (int)fminf(fmaxf(rintf(f), -128.f), 127.f);
}

template<int KROW>
__global__ void quant_act(const float* __restrict__ in, int8_t* __restrict__ q,
                          float* __restrict__ rowdq) {
    constexpr int PER = KROW / 1024;
    int row = blockIdx.x, tid = threadIdx.x;
    const float4* rp = reinterpret_cast<const float4*>(in + (size_t)row * KROW);
    float4 v[PER];
    float m = 0.f;
    #pragma unroll
    for (int j = 0; j < PER; j++) {
        v[j] = rp[tid + j * 256];
        m = fmaxf(m, fmaxf(fmaxf(fabsf(v[j].x), fabsf(v[j].y)), fmaxf(fabsf(v[j].z), fabsf(v[j].w))));
    }
    #pragma unroll
    for (int o = 16; o > 0; o >>= 1) m = fmaxf(m, __shfl_xor_sync(0xffffffffu, m, o));
    __shared__ float wm[8];
    if ((tid & 31) == 0) wm[tid >> 5] = m;
    __syncthreads();
    m = wm[0];
    #pragma unroll
    for (int k = 1; k < 8; k++) m = fmaxf(m, wm[k]);
    float sc = 127.0f / fmaxf(m, EPSF);
    int8_t* qp = q + (size_t)row * KROW;
    #pragma unroll
    for (int j = 0; j < PER; j++) {
        char4 p;
        p.x = (char)qcl(v[j].x * sc);
        p.y = (char)qcl(v[j].y * sc);
        p.z = (char)qcl(v[j].z * sc);
        p.w = (char)qcl(v[j].w * sc);
        reinterpret_cast<char4*>(qp)[tid + j * 256] = p;
    }
    if (tid == 0) rowdq[row] = 1.0f / sc;
}

// ---------------- int8 GEMM ----------------
// out[m,n] = (sum_k A[m,k]*B[n,k]) * rowdq[m] * wmean   (+ optional exact GELU)
// A: [M,K] int8 row-major, B: [N,K] int8 row-major, K % 64 == 0.
__device__ __forceinline__ float gelu_exact(float v) {
    return 0.5f * v * (1.0f + erff(v * 0.70710678118654752440f));
}

static constexpr int STAGES = 4;
static constexpr int STAGE_BYTES = 16384;                 // 8KB A + 8KB B
static constexpr size_t GEMM_SMEM = STAGES * STAGE_BYTES; // 64KB

__device__ __forceinline__ void stage_copy(const int8_t* A, const int8_t* B, int K,
                                           int m0, int n0, int kt, uint32_t sbase, int tid) {
    #pragma unroll
    for (int h = 0; h < 2; h++) {
        int q = tid + h * 256;
        int row = q >> 2, c = q & 3;
        const int8_t* srcA = A + (size_t)(m0 + row) * K + kt + c * 16;
        uint32_t dstA = sbase + row * 64 + (((c ^ ((row >> 1) & 3))) << 4);
        CP_ASYNC16(dstA, srcA);
        const int8_t* srcB = B + (size_t)(n0 + row) * K + kt + c * 16;
        uint32_t dstB = sbase + 8192 + row * 64 + (((c ^ ((row >> 1) & 3))) << 4);
        CP_ASYNC16(dstB, srcB);
    }
}

template<bool GELU>
__global__ __launch_bounds__(256, 1)
void bit_gemm_i8(const int8_t* __restrict__ A, const int8_t* __restrict__ B,
                 float* __restrict__ out, const float* __restrict__ rowdq,
                 const float* __restrict__ wmeanp, int N, int K) {
    extern __shared__ int8_t smem_raw[];
    const uint32_t sb = smem_u32(smem_raw);
    const int tid  = threadIdx.x;
    const int lane = tid & 31;
    const int warp = tid >> 5;
    const int wm = warp & 1;        // 2 warps along M (64 each)
    const int wn = warp >> 1;       // 4 warps along N (32 each)
    const int m0 = blockIdx.y * 128;
    const int n0 = blockIdx.x * 128;

    const int sub = lane & 7;
    const int mat = lane >> 3;
    // A ldmatrix lane geometry (per m-tile): rows wm*64 + mt*16 + sub + (mat&1)*8, chunk (kb/16)+(mat>>1)
    const int a_row0 = wm * 64 + sub + ((mat & 1) << 3);
    const int a_cadd = mat >> 1;
    const int a_sel  = (a_row0 >> 1) & 3;   // mt*16 doesn't change (row>>1)&3
    // B ldmatrix lane geometry (per 16-wide n-half): rows wn*32 + half*16 + (mat>>1)*8 + sub, chunk (kb/16)+(mat&1)
    const int b_row0 = wn * 32 + ((mat >> 1) << 3) + sub;
    const int b_cadd = mat & 1;
    const int b_sel  = (b_row0 >> 1) & 3;

    const int iters = K >> 6;

    // prologue: 3 stages in flight
    #pragma unroll
    for (int s = 0; s < 3; s++) {
        stage_copy(A, B, K, m0, n0, s * 64, sb + s * STAGE_BYTES, tid);
        CP_COMMIT();
    }

    int acc[4][4][4];
    #pragma unroll
    for (int i = 0; i < 4; i++)
        #pragma unroll
        for (int j = 0; j < 4; j++)
            #pragma unroll
            for (int k = 0; k < 4; k++) acc[i][j][k] = 0;

    for (int it = 0; it < iters; it++) {
        CP_WAIT(2);
        __syncthreads();
        const uint32_t abase = sb + (it & (STAGES - 1)) * STAGE_BYTES;
        const uint32_t bbase = abase + 8192;

        #pragma unroll
        for (int kb2 = 0; kb2 < 2; kb2++) {      // two k32 steps per BK=64
            const int kc = kb2 * 2;              // chunk offset = kb/16
            uint32_t a[4][4];
            #pragma unroll
            for (int mt = 0; mt < 4; mt++) {
                uint32_t addr = abase + (a_row0 + mt * 16) * 64 + (((kc + a_cadd) ^ a_sel) << 4);
                ldm_x4(a[mt][0], a[mt][1], a[mt][2], a[mt][3], addr);
            }
            uint32_t bf[2][4];
            #pragma unroll
            for (int h = 0; h < 2; h++) {
                uint32_t addr = bbase + (b_row0 + h * 16) * 64 + (((kc + b_cadd) ^ b_sel) << 4);
                ldm_x4(bf[h][0], bf[h][1], bf[h][2], bf[h][3], addr);
            }
            #pragma unroll
            for (int mt = 0; mt < 4; mt++) {
                #pragma unroll
                for (int nt = 0; nt < 4; nt++) {
                    // bf[nt/2]: regs {b0(t0), b1(t0), b0(t1), b1(t1)} for the two n8 tiles
                    imma(acc[mt][nt], a[mt], bf[nt >> 1][(nt & 1) << 1], bf[nt >> 1][((nt & 1) << 1) + 1]);
                }
            }
        }
        if (it + 3 < iters)
            stage_copy(A, B, K, m0, n0, (it + 3) * 64, sb + ((it + 3) & (STAGES - 1)) * STAGE_BYTES, tid);
        CP_COMMIT();
    }

    // epilogue
    const float wmean = wmeanp[0];
    const int g = lane >> 2;
    const int colq = (lane & 3) << 1;
    #pragma unroll
    for (int mt = 0; mt < 4; mt++) {
        int r0 = m0 + wm * 64 + mt * 16 + g;
        float dq0 = rowdq[r0] * wmean;
        float dq1 = rowdq[r0 + 8] * wmean;
        #pragma unroll
        for (int nt = 0; nt < 4; nt++) {
            int col = n0 + wn * 32 + nt * 8 + colq;
            float2 v0, v1;
            v0.x = (float)acc[mt][nt][0] * dq0;
            v0.y = (float)acc[mt][nt][1] * dq0;
            v1.x = (float)acc[mt][nt][2] * dq1;
            v1.y = (float)acc[mt][nt][3] * dq1;
            if (GELU) {
                v0.x = gelu_exact(v0.x); v0.y = gelu_exact(v0.y);
                v1.x = gelu_exact(v1.x); v1.y = gelu_exact(v1.y);
            }
            *reinterpret_cast<float2*>(out + (size_t)r0 * N + col) = v0;
            *reinterpret_cast<float2*>(out + (size_t)(r0 + 8) * N + col) = v1;
        }
    }
}

// ---------------- host ----------------
extern "C" void kernel_launch(void* const* d_in, const int* in_sizes, int n_in,
                              void* d_out, int out_size) {
    const float* x  = (const float*)d_in[0];
    const float* w1 = (const float*)d_in[1];
    const float* w2 = (const float*)d_in[2];
    float* out = (float*)d_out;

    void *p_xq, *p_w1q, *p_w2q, *p_h, *p_hq, *p_rdq1, *p_rdq2, *p_wmean, *p_part;
    cudaGetSymbolAddress(&p_xq, g_xq);
    cudaGetSymbolAddress(&p_w1q, g_w1q);
    cudaGetSymbolAddress(&p_w2q, g_w2q);
    cudaGetSymbolAddress(&p_h, g_h);
    cudaGetSymbolAddress(&p_hq, g_hq);
    cudaGetSymbolAddress(&p_rdq1, g_rdq1);
    cudaGetSymbolAddress(&p_rdq2, g_rdq2);
    cudaGetSymbolAddress(&p_wmean, g_wmean);
    cudaGetSymbolAddress(&p_part, g_part);

    cudaFuncSetAttribute(bit_gemm_i8<true>,  cudaFuncAttributeMaxDynamicSharedMemorySize, (int)GEMM_SMEM);
    cudaFuncSetAttribute(bit_gemm_i8<false>, cudaFuncAttributeMaxDynamicSharedMemorySize, (int)GEMM_SMEM);

    // weight scales (deterministic two-stage mean|w|), weight + activation quant
    absmean_partial<<<2048, 256>>>(w1, NWELEM, (float*)p_part);
    absmean_final<<<1, 256>>>((float*)p_part, 1.0f / (float)NWELEM, (float*)p_wmean + 0);
    absmean_partial<<<2048, 256>>>(w2, NWELEM, (float*)p_part + 2048);
    absmean_final<<<1, 256>>>((float*)p_part + 2048, 1.0f / (float)NWELEM, (float*)p_wmean + 1);
    quant_w<<<NWELEM / 1024, 256>>>(w1, (float*)p_wmean + 0, (int8_t*)p_w1q);
    quant_w<<<NWELEM / 1024, 256>>>(w2, (float*)p_wmean + 1, (int8_t*)p_w2q);
    quant_act<DMODEL><<<TOKENS, 256>>>(x, (int8_t*)p_xq, (float*)p_rdq1);

    // GEMM1: h = gelu( (xq @ w1q^T) * rdq1 * wmean1 )  [8192, 8192] f32
    dim3 g1(DHIDDEN / 128, TOKENS / 128);
    bit_gemm_i8<true><<<g1, 256, GEMM_SMEM>>>((const int8_t*)p_xq, (const int8_t*)p_w1q,
                                              (float*)p_h, (const float*)p_rdq1,
                                              (const float*)p_wmean + 0, DHIDDEN, DMODEL);

    // re-quantize h
    quant_act<DHIDDEN><<<TOKENS, 256>>>((const float*)p_h, (int8_t*)p_hq, (float*)p_rdq2);

    // GEMM2: out = (hq @ w2q^T) * rdq2 * wmean2  [8192, 2048] f32
    dim3 g2(DMODEL / 128, TOKENS / 128);
    bit_gemm_i8<false><<<g2, 256, GEMM_SMEM>>>((const int8_t*)p_hq, (const int8_t*)p_w2q,
                                               out, (const float*)p_rdq2,
                                               (const float*)p_wmean + 1, DMODEL, DHIDDEN);
}

// round 4
// speedup vs baseline: 1.0008x; 1.0008x over previous
#include <cuda_runtime.h>
#include <cuda.h>
#include <cstdint>
#include <cstddef>

static constexpr int DMODEL  = 2048;
static constexpr int DHIDDEN = 8192;
static constexpr int TOKENS  = 8192;
static constexpr int NWELEM  = DMODEL * DHIDDEN;  // 2^24
#define EPSF 1e-5f

__device__ __align__(128) int8_t g_xq[(size_t)TOKENS * DMODEL];
__device__ __align__(128) int8_t g_w1q[(size_t)NWELEM];
__device__ __align__(128) int8_t g_w2q[(size_t)NWELEM];
__device__ __align__(128) float  g_h[(size_t)TOKENS * DHIDDEN];
__device__ __align__(128) int8_t g_hq[(size_t)TOKENS * DHIDDEN];
__device__ float g_rdq1[TOKENS];
__device__ float g_rdq2[TOKENS];
__device__ float g_wmean[2];
__device__ float g_part[4096];

__device__ __forceinline__ uint32_t smem_u32(const void* p) {
    uint32_t a;
    asm("{ .reg .u64 t; cvta.to.shared.u64 t, %1; cvt.u32.u64 %0, t; }" : "=r"(a) : "l"(p));
    return a;
}
#define CP_ASYNC16(dst, src) \
    asm volatile("cp.async.cg.shared.global [%0], [%1], 16;" :: "r"(dst), "l"(src) : "memory")
#define CP_COMMIT() asm volatile("cp.async.commit_group;" ::: "memory")
#define CP_WAIT(n)  asm volatile("cp.async.wait_group %0;" :: "n"(n) : "memory")

__device__ __forceinline__ void ldm_x4(uint32_t& r0, uint32_t& r1, uint32_t& r2, uint32_t& r3,
                                       uint32_t addr) {
    asm volatile("ldmatrix.sync.aligned.m8n8.x4.shared.b16 {%0,%1,%2,%3}, [%4];"
        : "=r"(r0), "=r"(r1), "=r"(r2), "=r"(r3) : "r"(addr));
}
__device__ __forceinline__ void imma(int* d, const uint32_t* a, uint32_t b0, uint32_t b1) {
    asm volatile(
        "mma.sync.aligned.m16n8k32.row.col.s32.s8.s8.s32 "
        "{%0,%1,%2,%3}, {%4,%5,%6,%7}, {%8,%9}, {%0,%1,%2,%3};"
        : "+r"(d[0]), "+r"(d[1]), "+r"(d[2]), "+r"(d[3])
        : "r"(a[0]), "r"(a[1]), "r"(a[2]), "r"(a[3]), "r"(b0), "r"(b1));
}

// ---------------- small kernels ----------------
__global__ void absmean_partial(const float* __restrict__ w, int n, float* __restrict__ part) {
    float s = 0.f;
    for (int i = blockIdx.x * blockDim.x + threadIdx.x; i < n; i += gridDim.x * blockDim.x)
        s += fabsf(w[i]);
    __shared__ float sh[256];
    sh[threadIdx.x] = s;
    __syncthreads();
    #pragma unroll
    for (int o = 128; o > 0; o >>= 1) {
        if (threadIdx.x < o) sh[threadIdx.x] += sh[threadIdx.x + o];
        __syncthreads();
    }
    if (threadIdx.x == 0) part[blockIdx.x] = sh[0];
}

__global__ void absmean_final(const float* __restrict__ part, float invn, float* __restrict__ outp) {
    float s = 0.f;
    for (int i = threadIdx.x; i < 2048; i += 256) s += part[i];
    __shared__ float sh[256];
    sh[threadIdx.x] = s;
    __syncthreads();
    #pragma unroll
    for (int o = 128; o > 0; o >>= 1) {
        if (threadIdx.x < o) sh[threadIdx.x] += sh[threadIdx.x + o];
        __syncthreads();
    }
    if (threadIdx.x == 0) outp[0] = fmaxf(s = sh[0] * invn, EPSF);
}

__global__ void quant_w(const float* __restrict__ w, const float* __restrict__ meanp,
                        int8_t* __restrict__ wq) {
    float sc = 1.0f / meanp[0];
    int i = blockIdx.x * blockDim.x + threadIdx.x;
    float4 v = reinterpret_cast<const float4*>(w)[i];
    char4 p;
    p.x = (char)(int)fminf(fmaxf(rintf(v.x * sc), -1.f), 1.f);
    p.y = (char)(int)fminf(fmaxf(rintf(v.y * sc), -1.f), 1.f);
    p.z = (char)(int)fminf(fmaxf(rintf(v.z * sc), -1.f), 1.f);
    p.w = (char)(int)fminf(fmaxf(rintf(v.w * sc), -1.f), 1.f);
    reinterpret_cast<char4*>(wq)[i] = p;
}

__device__ __forceinline__ int qcl(float f) {
    return (int)fminf(fmaxf(rintf(f), -128.f), 127.f);
}

template<int KROW>
__global__ void quant_act(const float* __restrict__ in, int8_t* __restrict__ q,
                          float* __restrict__ rowdq) {
    constexpr int PER = KROW / 1024;
    int row = blockIdx.x, tid = threadIdx.x;
    const float4* rp = reinterpret_cast<const float4*>(in + (size_t)row * KROW);
    float4 v[PER];
    float m = 0.f;
    #pragma unroll
    for (int j = 0; j < PER; j++) {
        v[j] = rp[tid + j * 256];
        m = fmaxf(m, fmaxf(fmaxf(fabsf(v[j].x), fabsf(v[j].y)), fmaxf(fabsf(v[j].z), fabsf(v[j].w))));
    }
    #pragma unroll
    for (int o = 16; o > 0; o >>= 1) m = fmaxf(m, __shfl_xor_sync(0xffffffffu, m, o));
    __shared__ float wm[8];
    if ((tid & 31) == 0) wm[tid >> 5] = m;
    __syncthreads();
    m = wm[0];
    #pragma unroll
    for (int k = 1; k < 8; k++) m = fmaxf(m, wm[k]);
    float sc = 127.0f / fmaxf(m, EPSF);
    int8_t* qp = q + (size_t)row * KROW;
    #pragma unroll
    for (int j = 0; j < PER; j++) {
        char4 p;
        p.x = (char)qcl(v[j].x * sc);
        p.y = (char)qcl(v[j].y * sc);
        p.z = (char)qcl(v[j].z * sc);
        p.w = (char)qcl(v[j].w * sc);
        reinterpret_cast<char4*>(qp)[tid + j * 256] = p;
    }
    if (tid == 0) rowdq[row] = 1.0f / sc;
}

// ---------------- int8 GEMM ----------------
// out[m,n] = (sum_k A[m,k]*B[n,k]) * rowdq[m] * wmean   (+ optional exact GELU)
// A: [M,K] int8 row-major, B: [N,K] int8 row-major, K % 64 == 0.
__device__ __forceinline__ float gelu_exact(float v) {
    return 0.5f * v * (1.0f + erff(v * 0.70710678118654752440f));
}

static constexpr int STAGES = 4;
static constexpr int STAGE_BYTES = 16384;                 // 8KB A + 8KB B
static constexpr size_t GEMM_SMEM = STAGES * STAGE_BYTES; // 64KB

__device__ __forceinline__ void stage_copy(const int8_t* A, const int8_t* B, int K,
                                           int m0, int n0, int kt, uint32_t sbase, int tid) {
    #pragma unroll
    for (int h = 0; h < 2; h++) {
        int q = tid + h * 256;
        int row = q >> 2, c = q & 3;
        const int8_t* srcA = A + (size_t)(m0 + row) * K + kt + c * 16;
        uint32_t dstA = sbase + row * 64 + (((c ^ ((row >> 1) & 3))) << 4);
        CP_ASYNC16(dstA, srcA);
        const int8_t* srcB = B + (size_t)(n0 + row) * K + kt + c * 16;
        uint32_t dstB = sbase + 8192 + row * 64 + (((c ^ ((row >> 1) & 3))) << 4);
        CP_ASYNC16(dstB, srcB);
    }
}

template<bool GELU>
__global__ __launch_bounds__(256, 1)
void bit_gemm_i8(const int8_t* __restrict__ A, const int8_t* __restrict__ B,
                 float* __restrict__ out, const float* __restrict__ rowdq,
                 const float* __restrict__ wmeanp, int N, int K) {
    extern __shared__ int8_t smem_raw[];
    const uint32_t sb = smem_u32(smem_raw);
    const int tid  = threadIdx.x;
    const int lane = tid & 31;
    const int warp = tid >> 5;
    const int wm = warp & 1;        // 2 warps along M (64 each)
    const int wn = warp >> 1;       // 4 warps along N (32 each)
    const int m0 = blockIdx.y * 128;
    const int n0 = blockIdx.x * 128;

    const int sub = lane & 7;
    const int mat = lane >> 3;
    // A ldmatrix lane geometry (per m-tile): rows wm*64 + mt*16 + sub + (mat&1)*8, chunk (kb/16)+(mat>>1)
    const int a_row0 = wm * 64 + sub + ((mat & 1) << 3);
    const int a_cadd = mat >> 1;
    const int a_sel  = (a_row0 >> 1) & 3;   // mt*16 doesn't change (row>>1)&3
    // B ldmatrix lane geometry (per 16-wide n-half): rows wn*32 + half*16 + (mat>>1)*8 + sub, chunk (kb/16)+(mat&1)
    const int b_row0 = wn * 32 + ((mat >> 1) << 3) + sub;
    const int b_cadd = mat & 1;
    const int b_sel  = (b_row0 >> 1) & 3;

    const int iters = K >> 6;

    // prologue: 3 stages in flight
    #pragma unroll
    for (int s = 0; s < 3; s++) {
        stage_copy(A, B, K, m0, n0, s * 64, sb + s * STAGE_BYTES, tid);
        CP_COMMIT();
    }

    int acc[4][4][4];
    #pragma unroll
    for (int i = 0; i < 4; i++)
        #pragma unroll
        for (int j = 0; j < 4; j++)
            #pragma unroll
            for (int k = 0; k < 4; k++) acc[i][j][k] = 0;

    for (int it = 0; it < iters; it++) {
        CP_WAIT(2);
        __syncthreads();
        const uint32_t abase = sb + (it & (STAGES - 1)) * STAGE_BYTES;
        const uint32_t bbase = abase + 8192;

        #pragma unroll
        for (int kb2 = 0; kb2 < 2; kb2++) {      // two k32 steps per BK=64
            const int kc = kb2 * 2;              // chunk offset = kb/16
            uint32_t a[4][4];
            #pragma unroll
            for (int mt = 0; mt < 4; mt++) {
                uint32_t addr = abase + (a_row0 + mt * 16) * 64 + (((kc + a_cadd) ^ a_sel) << 4);
                ldm_x4(a[mt][0], a[mt][1], a[mt][2], a[mt][3], addr);
            }
            uint32_t bf[2][4];
            #pragma unroll
            for (int h = 0; h < 2; h++) {
                uint32_t addr = bbase + (b_row0 + h * 16) * 64 + (((kc + b_cadd) ^ b_sel) << 4);
                ldm_x4(bf[h][0], bf[h][1], bf[h][2], bf[h][3], addr);
            }
            #pragma unroll
            for (int mt = 0; mt < 4; mt++) {
                #pragma unroll
                for (int nt = 0; nt < 4; nt++) {
                    // bf[nt/2]: regs {b0(t0), b1(t0), b0(t1), b1(t1)} for the two n8 tiles
                    imma(acc[mt][nt], a[mt], bf[nt >> 1][(nt & 1) << 1], bf[nt >> 1][((nt & 1) << 1) + 1]);
                }
            }
        }
        if (it + 3 < iters)
            stage_copy(A, B, K, m0, n0, (it + 3) * 64, sb + ((it + 3) & (STAGES - 1)) * STAGE_BYTES, tid);
        CP_COMMIT();
    }

    // epilogue
    const float wmean = wmeanp[0];
    const int g = lane >> 2;
    const int colq = (lane & 3) << 1;
    #pragma unroll
    for (int mt = 0; mt < 4; mt++) {
        int r0 = m0 + wm * 64 + mt * 16 + g;
        float dq0 = rowdq[r0] * wmean;
        float dq1 = rowdq[r0 + 8] * wmean;
        #pragma unroll
        for (int nt = 0; nt < 4; nt++) {
            int col = n0 + wn * 32 + nt * 8 + colq;
            float2 v0, v1;
            v0.x = (float)acc[mt][nt][0] * dq0;
            v0.y = (float)acc[mt][nt][1] * dq0;
            v1.x = (float)acc[mt][nt][2] * dq1;
            v1.y = (float)acc[mt][nt][3] * dq1;
            if (GELU) {
                v0.x = gelu_exact(v0.x); v0.y = gelu_exact(v0.y);
                v1.x = gelu_exact(v1.x); v1.y = gelu_exact(v1.y);
            }
            *reinterpret_cast<float2*>(out + (size_t)r0 * N + col) = v0;
            *reinterpret_cast<float2*>(out + (size_t)(r0 + 8) * N + col) = v1;
        }
    }
}

// ---------------- host ----------------
extern "C" void kernel_launch(void* const* d_in, const int* in_sizes, int n_in,
                              void* d_out, int out_size) {
    const float* x  = (const float*)d_in[0];
    const float* w1 = (const float*)d_in[1];
    const float* w2 = (const float*)d_in[2];
    float* out = (float*)d_out;

    void *p_xq, *p_w1q, *p_w2q, *p_h, *p_hq, *p_rdq1, *p_rdq2, *p_wmean, *p_part;
    cudaGetSymbolAddress(&p_xq, g_xq);
    cudaGetSymbolAddress(&p_w1q, g_w1q);
    cudaGetSymbolAddress(&p_w2q, g_w2q);
    cudaGetSymbolAddress(&p_h, g_h);
    cudaGetSymbolAddress(&p_hq, g_hq);
    cudaGetSymbolAddress(&p_rdq1, g_rdq1);
    cudaGetSymbolAddress(&p_rdq2, g_rdq2);
    cudaGetSymbolAddress(&p_wmean, g_wmean);
    cudaGetSymbolAddress(&p_part, g_part);

    cudaFuncSetAttribute(bit_gemm_i8<true>,  cudaFuncAttributeMaxDynamicSharedMemorySize, (int)GEMM_SMEM);
    cudaFuncSetAttribute(bit_gemm_i8<false>, cudaFuncAttributeMaxDynamicSharedMemorySize, (int)GEMM_SMEM);

    // weight scales (deterministic two-stage mean|w|), weight + activation quant
    absmean_partial<<<2048, 256>>>(w1, NWELEM, (float*)p_part);
    absmean_final<<<1, 256>>>((float*)p_part, 1.0f / (float)NWELEM, (float*)p_wmean + 0);
    absmean_partial<<<2048, 256>>>(w2, NWELEM, (float*)p_part + 2048);
    absmean_final<<<1, 256>>>((float*)p_part + 2048, 1.0f / (float)NWELEM, (float*)p_wmean + 1);
    quant_w<<<NWELEM / 1024, 256>>>(w1, (float*)p_wmean + 0, (int8_t*)p_w1q);
    quant_w<<<NWELEM / 1024, 256>>>(w2, (float*)p_wmean + 1, (int8_t*)p_w2q);
    quant_act<DMODEL><<<TOKENS, 256>>>(x, (int8_t*)p_xq, (float*)p_rdq1);

    // GEMM1: h = gelu( (xq @ w1q^T) * rdq1 * wmean1 )  [8192, 8192] f32
    dim3 g1(DHIDDEN / 128, TOKENS / 128);
    bit_gemm_i8<true><<<g1, 256, GEMM_SMEM>>>((const int8_t*)p_xq, (const int8_t*)p_w1q,
                                              (float*)p_h, (const float*)p_rdq1,
                                              (const float*)p_wmean + 0, DHIDDEN, DMODEL);

    // re-quantize h
    quant_act<DHIDDEN><<<TOKENS, 256>>>((const float*)p_h, (int8_t*)p_hq, (float*)p_rdq2);

    // GEMM2: out = (hq @ w2q^T) * rdq2 * wmean2  [8192, 2048] f32
    dim3 g2(DMODEL / 128, TOKENS / 128);
    bit_gemm_i8<false><<<g2, 256, GEMM_SMEM>>>((const int8_t*)p_hq, (const int8_t*)p_w2q,
                                               out, (const float*)p_rdq2,
                                               (const float*)p_wmean + 1, DMODEL, DHIDDEN);
}